// round 16
// baseline (speedup 1.0000x reference)
#include <cuda_runtime.h>
#include <math.h>
#include <cstdio>

// ---------------------------------------------------------------------------
// QuantPINN: dedup inputs to distinct int8 pairs; 7-layer quantized MLP in
// ONE persistent kernel with SMEM-RESIDENT activations (148 blocks, 1/SM,
// 512 thr, ~151KB smem; each block owns ~cnt/148 rows for the whole net).
// Tensor-core s8 GEMMs (m16n8k32, K padded, exact). Quantization: Newton-
// built breakpoints Tp + coarse bit-LUT C (no MUFU in per-element path).
// R16: B-fragments via direct LDG from g_Wp (no smem staging); output table
// indexed BY CODE (P9 gather = single random hop); clock64 phase print.
// ---------------------------------------------------------------------------

#define N_MAX   262144
#define HID     100
#define KG      25
#define KGP     32
#define QMAXF   127.0f
#define NCODE   65025
#define NBLK    148
#define NTHR    512
#define GSTRIDE (NBLK * NTHR)
#define CAP     256
#define CAPP    260
#define CLUT    832
#define CBASE   7552

// dynamic smem layout (bytes)
#define YB_OFF  0            // float yb[CAP][100]          102400
#define XS_OFF  102400       // int   Xs[32][CAPP]           33280
#define WS_OFF  135680       // int   Ws (layer1 only)        1024
#define TP_OFF  136704       // float Tp[130]                  528
#define C_OFF   137232       // uchar C[CLUT]                  832
#define BQ_OFF  138064       // float bqs[104]                 416
#define RED_OFF 138480       // float red[16]                   64
#define SCL_OFF 138544       // float scl[2]                     8
#define SMEM_TOTAL 138560

__device__ int   g_Wp[5][KGP][104];
__device__ int   g_W1i[HID * 2];
__device__ int   g_Wpo[2][KG];
__device__ float g_sw[7];
__device__ int   g_slots[8];
__device__ int   g_code[N_MAX];
__device__ int   g_present[NCODE];
__device__ int   g_gen;
__device__ int   g_list[NCODE];
__device__ int   g_cnt;
__device__ float g_table2[NCODE * 2];   // indexed BY CODE
__device__ int   g_bar_cnt;
__device__ int   g_bar_sense;

// ---------------------------------------------------------------------------
__device__ __forceinline__ float xla_tanh(float x) {
    const float kMax = 7.90531110763549805f;
    float xc = fmaxf(-kMax, fminf(x, kMax));
    float x2 = __fmul_rn(xc, xc);
    float p = -2.76076847742355e-16f;
    p = __fadd_rn(__fmul_rn(p, x2), 2.00018790482477e-13f);
    p = __fadd_rn(__fmul_rn(p, x2), -8.60467152213735e-11f);
    p = __fadd_rn(__fmul_rn(p, x2), 5.12229709037114e-08f);
    p = __fadd_rn(__fmul_rn(p, x2), 1.48572235717979e-05f);
    p = __fadd_rn(__fmul_rn(p, x2), 6.37261928875436e-04f);
    p = __fadd_rn(__fmul_rn(p, x2), 4.89352455891786e-03f);
    float num = __fmul_rn(xc, p);
    float q = 1.19825839466702e-06f;
    q = __fadd_rn(__fmul_rn(q, x2), 1.18534705686654e-04f);
    q = __fadd_rn(__fmul_rn(q, x2), 2.26843463243900e-03f);
    q = __fadd_rn(__fmul_rn(q, x2), 4.89352518554385e-03f);
    float r = __fdiv_rn(num, q);
    return (fabsf(x) < 0.0004f) ? x : r;
}

__device__ __forceinline__ float scale_in() {
    float m = __int_as_float(g_slots[0]);
    return fmaxf(__fdiv_rn(m, QMAXF), 1e-12f);
}
__device__ __forceinline__ float scale_act(int slot) {
    float m = __int_as_float(g_slots[slot]);
    float mh = xla_tanh(m);
    return fmaxf(__fdiv_rn(mh, QMAXF), 1e-12f);
}

__device__ __forceinline__ int q8(float v, float s) {
    float x = __fdiv_rn(v, s);
    x = fminf(fmaxf(x, -127.0f), 127.0f);
    return __float2int_rn(x);
}
__device__ __forceinline__ int q8f(float v, float s, float inv) {
    float r = __fmul_rn(v, inv);
    float rr = rintf(r);
    float d = fabsf(__fadd_rn(r, -rr));
    if (fabsf(d - 0.5f) < (4e-7f * fabsf(r) + 1e-9f))
        r = __fdiv_rn(v, s);
    r = fminf(fmaxf(r, -127.0f), 127.0f);
    return __float2int_rn(r);
}
__device__ __forceinline__ int pack4(int a, int b, int c, int d) {
    return (a & 0xFF) | ((b & 0xFF) << 8) | ((c & 0xFF) << 16) | ((d & 0xFF) << 24);
}
__device__ __forceinline__ float bias_q(float b, float sb) {
    float r = rintf(__fdiv_rn(b, sb));
    r = fminf(fmaxf(r, -128.0f), 127.0f);
    return __fmul_rn(r, sb);
}

__device__ __forceinline__ void build_Tp(float s, float* Tp) {
    int tid = threadIdx.x;
    if (tid < 130) {
        float v;
        if (tid == 0)        v = 0.0f;
        else if (tid >= 128) v = 3.0e38f;
        else {
            float tstar = __fmul_rn((float)tid - 0.5f, s);
            float r = __fdividef(1.0f + tstar, 1.0f - tstar);
            float y = 0.5f * __logf(r);
            #pragma unroll
            for (int it = 0; it < 2; it++) {
                float th = xla_tanh(y);
                float dv = fmaxf(1.0f - th * th, 1e-30f);
                y = y - __fdividef(th - tstar, dv);
            }
            v = y;
        }
        Tp[tid] = v;
    }
}

__device__ __forceinline__ void build_C(const float* Tp, unsigned char* C) {
    for (int e = threadIdx.x; e < CLUT; e += NTHR) {
        float yl = __uint_as_float(((unsigned)(e + CBASE)) << 17);
        int pos = 0;
        #pragma unroll
        for (int w = 64; w > 0; w >>= 1) {
            int j = pos + w;
            if (j <= 127 && Tp[j] <= yl) pos = j;
        }
        C[e] = (unsigned char)pos;
    }
}

__device__ __forceinline__ int qlut(float y, const float* Tp, const unsigned char* C) {
    float a = fabsf(y);
    unsigned u = __float_as_uint(fminf(a, 8.4999f));
    int idx = (int)(u >> 17) - CBASE;
    idx = idx < 0 ? 0 : idx;
    int c = C[idx];
    c += (a >= Tp[c + 1]) ? 1 : 0;
    c += (a >= Tp[c + 1]) ? 1 : 0;
    return (__float_as_uint(y) & 0x80000000u) ? -c : c;
}

__device__ __forceinline__ void mma_s8(int& d0, int& d1, int& d2, int& d3,
                                       int a0, int a1, int a2, int a3,
                                       int b0, int b1) {
    asm volatile(
        "mma.sync.aligned.m16n8k32.row.col.s32.s8.s8.s32 "
        "{%0,%1,%2,%3}, {%4,%5,%6,%7}, {%8,%9}, {%0,%1,%2,%3};"
        : "+r"(d0), "+r"(d1), "+r"(d2), "+r"(d3)
        : "r"(a0), "r"(a1), "r"(a2), "r"(a3), "r"(b0), "r"(b1));
}

__device__ __forceinline__ void grid_bar(int& sense) {
    int s = sense ^ 1;
    __threadfence();
    __syncthreads();
    if (threadIdx.x == 0) {
        int a = atomicAdd(&g_bar_cnt, 1);
        if (a == NBLK - 1) {
            g_bar_cnt = 0;
            __threadfence();
            g_bar_sense = s;
            __threadfence();
        } else {
            while (*((volatile int*)&g_bar_sense) != s)
                __nanosleep(64);
        }
    }
    __syncthreads();
    __threadfence();
    sense = s;
}

__device__ __forceinline__ void block_max_atomic(float v, int slot, float* s_red) {
    #pragma unroll
    for (int off = 16; off > 0; off >>= 1)
        v = fmaxf(v, __shfl_xor_sync(0xffffffffu, v, off));
    int w = threadIdx.x >> 5;
    if ((threadIdx.x & 31) == 0) s_red[w] = v;
    __syncthreads();
    if (threadIdx.x == 0) {
        float m = s_red[0];
        #pragma unroll
        for (int i = 1; i < NTHR / 32; i++) m = fmaxf(m, s_red[i]);
        atomicMax(&g_slots[slot], __float_as_int(m));
    }
    __syncthreads();
}

// ---------------------------------------------------------------------------
__global__ void k_prep(const float* __restrict__ z, const float* __restrict__ t,
                       const float* __restrict__ W1,
                       const float* __restrict__ W2, const float* __restrict__ W3,
                       const float* __restrict__ W4, const float* __restrict__ W5,
                       const float* __restrict__ W6, const float* __restrict__ Wout,
                       int n) {
    __shared__ float red[256];
    int tid = threadIdx.x;
    int bid = blockIdx.x;

    if (bid < 256) {
        float m = 0.0f;
        for (int i = bid * 256 + tid; i < n; i += 256 * 256)
            m = fmaxf(m, fmaxf(fabsf(z[i]), fabsf(t[i])));
        #pragma unroll
        for (int off = 16; off > 0; off >>= 1)
            m = fmaxf(m, __shfl_xor_sync(0xffffffffu, m, off));
        if ((tid & 31) == 0) red[tid >> 5] = m;
        __syncthreads();
        if (tid == 0) {
            float mm = red[0];
            #pragma unroll
            for (int i = 1; i < 8; i++) mm = fmaxf(mm, red[i]);
            atomicMax(&g_slots[0], __float_as_int(mm));
        }
        return;
    }
    if (bid == 263) {
        if (tid == 0) {
            g_cnt = 0;
            g_bar_cnt = 0;
            g_bar_sense = 0;
            g_gen = g_gen + 1;
        }
        return;
    }

    int l = bid - 256;
    const float* W;
    int cnt;
    if (l == 0)      { W = W1;   cnt = HID * 2; }
    else if (l == 6) { W = Wout; cnt = 2 * HID; }
    else {
        const float* Ws_[5] = {W2, W3, W4, W5, W6};
        W = Ws_[l - 1]; cnt = HID * HID;
    }

    float m = 0.0f;
    for (int i = tid; i < cnt; i += 256) m = fmaxf(m, fabsf(W[i]));
    red[tid] = m;
    __syncthreads();
    for (int s = 128; s > 0; s >>= 1) {
        if (tid < s) red[tid] = fmaxf(red[tid], red[tid + s]);
        __syncthreads();
    }
    __shared__ float s_sw;
    if (tid == 0) {
        float sw = fmaxf(__fdiv_rn(red[0], QMAXF), 1e-12f);
        g_sw[l] = sw;
        s_sw = sw;
    }
    __syncthreads();
    float sw = s_sw;

    if (l == 0) {
        for (int i = tid; i < HID * 2; i += 256)
            g_W1i[i] = q8(W[i], sw);
    } else if (l == 6) {
        for (int w = tid; w < 2 * KG; w += 256) {
            int o = w / KG, kg = w % KG;
            int base = o * HID + kg * 4;
            g_Wpo[o][kg] = pack4(q8(W[base + 0], sw), q8(W[base + 1], sw),
                                 q8(W[base + 2], sw), q8(W[base + 3], sw));
        }
    } else {
        for (int w = tid; w < KGP * 104; w += 256) {
            int kg = w / 104, c = w % 104;
            int p = 0;
            if (kg < KG && c < HID) {
                int base = c * HID + kg * 4;
                p = pack4(q8(W[base + 0], sw), q8(W[base + 1], sw),
                          q8(W[base + 2], sw), q8(W[base + 3], sw));
            }
            g_Wp[l - 1][kg][c] = p;
        }
    }
}

// ---------------------------------------------------------------------------
__global__ void __launch_bounds__(NTHR, 1)
k_mega(const float* __restrict__ z, const float* __restrict__ t,
       const float* __restrict__ b1, const float* __restrict__ b2,
       const float* __restrict__ b3, const float* __restrict__ b4,
       const float* __restrict__ b5, const float* __restrict__ b6,
       const float* __restrict__ bout, float* __restrict__ out, int n) {
    extern __shared__ char smem[];
    float*         s_yb  = (float*)(smem + YB_OFF);
    int*           s_Xs  = (int*)(smem + XS_OFF);
    int*           s_Ws  = (int*)(smem + WS_OFF);
    float*         s_Tp  = (float*)(smem + TP_OFF);
    unsigned char* s_C   = (unsigned char*)(smem + C_OFF);
    float*         s_bqs = (float*)(smem + BQ_OFF);
    float*         s_red = (float*)(smem + RED_OFF);
    float*         s_scl = (float*)(smem + SCL_OFF);

    int tid  = threadIdx.x;
    int gtid = blockIdx.x * NTHR + tid;
    int sense = 0;
    int gen = g_gen;

    long long tmark[12];
    int tnum = 0;
    bool timer = (blockIdx.x == 0 && tid == 0);
    if (timer) tmark[tnum++] = clock64();

    // ---- P0: input codes + presence (x4 vectorized) -------------------------
    {
        if (tid == 0) {
            float sx = scale_in();
            s_scl[0] = sx;
            s_scl[1] = __fdiv_rn(1.0f, sx);
        }
        __syncthreads();
        float sx = s_scl[0];
        float inv = s_scl[1];
        int n4 = n >> 2;
        for (int i = gtid; i < n4; i += GSTRIDE) {
            float4 zv = ((const float4*)z)[i];
            float4 tv = ((const float4*)t)[i];
            int c0 = (q8f(zv.x, sx, inv) + 127) * 255 + (q8f(tv.x, sx, inv) + 127);
            int c1 = (q8f(zv.y, sx, inv) + 127) * 255 + (q8f(tv.y, sx, inv) + 127);
            int c2 = (q8f(zv.z, sx, inv) + 127) * 255 + (q8f(tv.z, sx, inv) + 127);
            int c3 = (q8f(zv.w, sx, inv) + 127) * 255 + (q8f(tv.w, sx, inv) + 127);
            ((int4*)g_code)[i] = make_int4(c0, c1, c2, c3);
            g_present[c0] = gen;
            g_present[c1] = gen;
            g_present[c2] = gen;
            g_present[c3] = gen;
        }
        for (int i = (n4 << 2) + gtid; i < n; i += GSTRIDE) {
            int zi = q8f(z[i], sx, inv);
            int ti = q8f(t[i], sx, inv);
            int c = (zi + 127) * 255 + (ti + 127);
            g_code[i] = c;
            g_present[c] = gen;
        }
    }
    grid_bar(sense);
    if (timer) tmark[tnum++] = clock64();

    // ---- P1: warp-aggregated compaction ------------------------------------
    {
        int lane = tid & 31;
        unsigned lt = (1u << lane) - 1u;
        int bound = ((NCODE + GSTRIDE - 1) / GSTRIDE) * GSTRIDE;
        for (int c = gtid; c < bound; c += GSTRIDE) {
            bool p = (c < NCODE) && (g_present[c] == gen);
            unsigned mask = __ballot_sync(0xffffffffu, p);
            int base = 0;
            if (lane == 0 && mask) base = atomicAdd(&g_cnt, __popc(mask));
            base = __shfl_sync(0xffffffffu, base, 0);
            if (p) {
                int j = base + __popc(mask & lt);
                g_list[j] = c;
            }
        }
    }
    grid_bar(sense);
    if (timer) tmark[tnum++] = clock64();
    int cnt = g_cnt;

    int chunk = (cnt + NBLK - 1) / NBLK;
    chunk = chunk < CAP ? chunk : CAP;
    int rbeg = blockIdx.x * chunk;
    int rend = rbeg + chunk;
    rend = rend < cnt ? rend : cnt;
    int nloc = rend - rbeg;
    nloc = nloc > 0 ? nloc : 0;
    int slabs = (nloc + 15) >> 4;

    // ---- P2: layer 1 -> y1 into block-local smem ----------------------------
    {
        if (tid == 0) s_scl[0] = __fmul_rn(scale_in(), g_sw[0]);
        if (tid < HID * 2) s_Ws[tid] = g_W1i[tid];
        __syncthreads();
        float sb = s_scl[0];
        if (tid < HID) s_bqs[tid] = bias_q(b1[tid], sb);
        __syncthreads();

        float vmax = 0.0f;
        int tot = nloc * 25;
        for (int idx = tid; idx < tot; idx += NTHR) {
            int r  = idx / 25;
            int og = idx - r * 25;
            int c  = g_list[rbeg + r];
            int hi = c / 255;
            int zi = hi - 127;
            int ti = (c - hi * 255) - 127;
            float4 hv;
            float* hp = &hv.x;
            #pragma unroll
            for (int j = 0; j < 4; j++) {
                int o = og * 4 + j;
                int acc = zi * s_Ws[o * 2] + ti * s_Ws[o * 2 + 1];
                float y = (float)acc * sb + s_bqs[o];
                hp[j] = y;
                vmax = fmaxf(vmax, fabsf(y));
            }
            ((float4*)(s_yb + r * HID))[og] = hv;
        }
        block_max_atomic(vmax, 1, s_red);
    }
    grid_bar(sense);
    if (timer) tmark[tnum++] = clock64();

    // ---- P3..P7: hidden layers 2..6 -----------------------------------------
    {
        const float* biases[5] = {b2, b3, b4, b5, b6};
        int lane = tid & 31, wrp = tid >> 5;
        int g = lane >> 2, tg = lane & 3;
        int cA = (wrp << 3) + (tg << 1);
        bool mmaok = (wrp < 13);
        bool colok = mmaok && (cA < HID);

        for (int l = 1; l <= 5; l++) {
            const float* bias = biases[l - 1];

            if (tid == 0) {
                float sx = scale_act(l);
                s_scl[0] = sx;
                s_scl[1] = __fmul_rn(sx, g_sw[l]);
            }

            // B-fragments direct from global (L2-resident) — no smem staging
            const int* wp = &g_Wp[l - 1][0][0];
            int bf0[4], bf1[4];
            if (mmaok) {
                #pragma unroll
                for (int kc = 0; kc < 4; kc++) {
                    bf0[kc] = wp[(8 * kc + tg) * 104 + (wrp << 3) + g];
                    bf1[kc] = wp[(8 * kc + tg + 4) * 104 + (wrp << 3) + g];
                }
            }
            __syncthreads();
            float sx = s_scl[0];
            float sb = s_scl[1];

            if (tid < 104)
                s_bqs[tid] = (tid < HID) ? bias_q(bias[tid], sb) : 0.0f;
            build_Tp(sx, s_Tp);
            __syncthreads();
            build_C(s_Tp, s_C);
            __syncthreads();

            int wtot = (slabs << 4) * KGP;
            for (int w = tid; w < wtot; w += NTHR) {
                int r = w >> 5, kg = w & 31;
                int p = 0;
                if (kg < KG && r < nloc) {
                    float4 v = ((const float4*)(s_yb + r * HID))[kg];
                    p = pack4(qlut(v.x, s_Tp, s_C), qlut(v.y, s_Tp, s_C),
                              qlut(v.z, s_Tp, s_C), qlut(v.w, s_Tp, s_C));
                }
                s_Xs[kg * CAPP + r] = p;
            }
            __syncthreads();

            float vmax = 0.0f;
            if (mmaok) {
                float bqA = colok ? s_bqs[cA] : 0.0f;
                float bqB = colok ? s_bqs[cA + 1] : 0.0f;

                for (int mt = 0; mt < slabs; mt++) {
                    int d0 = 0, d1 = 0, d2 = 0, d3 = 0;
                    int rbase = (mt << 4) + g;
                    #pragma unroll
                    for (int kc = 0; kc < 4; kc++) {
                        int a0 = s_Xs[(8 * kc + tg) * CAPP + rbase];
                        int a1 = s_Xs[(8 * kc + tg) * CAPP + rbase + 8];
                        int a2 = s_Xs[(8 * kc + tg + 4) * CAPP + rbase];
                        int a3 = s_Xs[(8 * kc + tg + 4) * CAPP + rbase + 8];
                        mma_s8(d0, d1, d2, d3, a0, a1, a2, a3, bf0[kc], bf1[kc]);
                    }
                    if (colok) {
                        if (rbase < nloc) {
                            float y0 = (float)d0 * sb + bqA;
                            float y1 = (float)d1 * sb + bqB;
                            vmax = fmaxf(vmax, fmaxf(fabsf(y0), fabsf(y1)));
                            *(float2*)(s_yb + rbase * HID + cA) = make_float2(y0, y1);
                        }
                        if (rbase + 8 < nloc) {
                            float y2 = (float)d2 * sb + bqA;
                            float y3 = (float)d3 * sb + bqB;
                            vmax = fmaxf(vmax, fmaxf(fabsf(y2), fabsf(y3)));
                            *(float2*)(s_yb + (rbase + 8) * HID + cA) = make_float2(y2, y3);
                        }
                    }
                }
            }
            block_max_atomic(vmax, l + 1, s_red);
            grid_bar(sense);
            if (timer) tmark[tnum++] = clock64();
        }
    }

    // ---- P8: output layer (smem y6 -> code-indexed table2) ------------------
    {
        if (tid == 0) {
            float sx = scale_act(6);
            s_scl[0] = sx;
            s_scl[1] = __fmul_rn(sx, g_sw[6]);
        }
        __syncthreads();
        float sx = s_scl[0];
        float sb = s_scl[1];
        float bq0 = bias_q(bout[0], sb);
        float bq1 = bias_q(bout[1], sb);

        build_Tp(sx, s_Tp);
        __syncthreads();
        build_C(s_Tp, s_C);
        __syncthreads();

        int wtot = (slabs << 4) * KGP;
        for (int w = tid; w < wtot; w += NTHR) {
            int r = w >> 5, kg = w & 31;
            int p = 0;
            if (kg < KG && r < nloc) {
                float4 v = ((const float4*)(s_yb + r * HID))[kg];
                p = pack4(qlut(v.x, s_Tp, s_C), qlut(v.y, s_Tp, s_C),
                          qlut(v.z, s_Tp, s_C), qlut(v.w, s_Tp, s_C));
            }
            s_Xs[kg * CAPP + r] = p;
        }
        __syncthreads();

        for (int idx = tid; idx < nloc * 2; idx += NTHR) {
            int r = idx >> 1, o = idx & 1;
            int acc = 0;
            #pragma unroll
            for (int kg = 0; kg < KG; kg++)
                acc = __dp4a(s_Xs[kg * CAPP + r], g_Wpo[o][kg], acc);
            int code = g_list[rbeg + r];
            g_table2[(size_t)code * 2 + o] = (float)acc * sb + (o ? bq1 : bq0);
        }
    }
    grid_bar(sense);
    if (timer) tmark[tnum++] = clock64();

    // ---- P9: gather, single random hop (x4 vectorized) ----------------------
    {
        int n4 = n >> 2;
        for (int i = gtid; i < n4; i += GSTRIDE) {
            int4 c = ((const int4*)g_code)[i];
            float2 r0 = ((const float2*)g_table2)[c.x];
            float2 r1 = ((const float2*)g_table2)[c.y];
            float2 r2 = ((const float2*)g_table2)[c.z];
            float2 r3 = ((const float2*)g_table2)[c.w];
            ((float4*)out)[i * 2]     = make_float4(r0.x, r0.y, r1.x, r1.y);
            ((float4*)out)[i * 2 + 1] = make_float4(r2.x, r2.y, r3.x, r3.y);
        }
        for (int i = (n4 << 2) + gtid; i < n; i += GSTRIDE) {
            ((float2*)out)[i] = ((const float2*)g_table2)[g_code[i]];
        }
    }
    if (timer) {
        tmark[tnum++] = clock64();
        printf("PHASES cnt=%d P0=%lld P1=%lld P2=%lld L2=%lld L3=%lld L4=%lld "
               "L5=%lld L6=%lld P8=%lld P9=%lld\n", cnt,
               tmark[1] - tmark[0], tmark[2] - tmark[1], tmark[3] - tmark[2],
               tmark[4] - tmark[3], tmark[5] - tmark[4], tmark[6] - tmark[5],
               tmark[7] - tmark[6], tmark[8] - tmark[7], tmark[9] - tmark[8],
               tmark[10] - tmark[9]);
    }
}

// ---------------------------------------------------------------------------

extern "C" void kernel_launch(void* const* d_in, const int* in_sizes, int n_in,
                              void* d_out, int out_size) {
    const float* z    = (const float*)d_in[0];
    const float* t    = (const float*)d_in[1];
    const float* W1   = (const float*)d_in[2];
    const float* b1   = (const float*)d_in[3];
    const float* W2   = (const float*)d_in[4];
    const float* b2   = (const float*)d_in[5];
    const float* W3   = (const float*)d_in[6];
    const float* b3   = (const float*)d_in[7];
    const float* W4   = (const float*)d_in[8];
    const float* b4   = (const float*)d_in[9];
    const float* W5   = (const float*)d_in[10];
    const float* b5   = (const float*)d_in[11];
    const float* W6   = (const float*)d_in[12];
    const float* b6   = (const float*)d_in[13];
    const float* Wout = (const float*)d_in[14];
    const float* bout = (const float*)d_in[15];
    int n = in_sizes[0];

    static int configured = 0;
    if (!configured) {
        cudaFuncSetAttribute(k_mega, cudaFuncAttributeMaxDynamicSharedMemorySize,
                             SMEM_TOTAL);
        configured = 1;
    }

    k_prep<<<264, 256>>>(z, t, W1, W2, W3, W4, W5, W6, Wout, n);
    k_mega<<<NBLK, NTHR, SMEM_TOTAL>>>(z, t, b1, b2, b3, b4, b5, b6, bout,
                                       (float*)d_out, n);
}

// round 17
// speedup vs baseline: 1.2212x; 1.2212x over previous
#include <cuda_runtime.h>
#include <math.h>

// ---------------------------------------------------------------------------
// QuantPINN: dedup inputs to distinct int8 pairs; 7-layer quantized MLP in
// ONE persistent kernel with SMEM-RESIDENT activations (148 blocks, 1/SM,
// 512 thr; each block owns ~cnt/148 rows for the whole net). Tensor-core s8
// GEMMs (m16n8k32, K padded, exact). Quantization: Newton-built breakpoints
// Tp + coarse bit-LUT C (no MUFU per element). R17 = R15 champion structure
// + code-indexed output table (P9 gather = single random hop, g_inv gone).
// ---------------------------------------------------------------------------

#define N_MAX   262144
#define HID     100
#define KG      25
#define KGP     32
#define QMAXF   127.0f
#define NCODE   65025
#define NBLK    148          // 1 block/SM -> co-resident
#define NTHR    512          // 16 warps; warps 0..12 own MMA columns
#define GSTRIDE (NBLK * NTHR)
#define CAP     256
#define CAPP    260
#define CLUT    832
#define CBASE   7552

// dynamic smem layout (bytes) — R15 layout
#define YB_OFF  0            // float yb[CAP][100]          102400
#define XS_OFF  102400       // int   Xs[32][CAPP]           33280
#define WS_OFF  135680       // int   Ws[32][104]            13312
#define TP_OFF  148992       // float Tp[130]                  528
#define C_OFF   149520       // uchar C[CLUT]                  832
#define BQ_OFF  150352       // float bqs[104]                 416
#define RED_OFF 150768       // float red[16]                   64
#define SCL_OFF 150832       // float scl[2]                     8
#define SMEM_TOTAL 150848

__device__ int   g_Wp[5][KGP][104];
__device__ int   g_W1i[HID * 2];
__device__ int   g_Wpo[2][KG];
__device__ float g_sw[7];
__device__ int   g_slots[8];
__device__ int   g_code[N_MAX];
__device__ int   g_present[NCODE];
__device__ int   g_gen;
__device__ int   g_list[NCODE];
__device__ int   g_cnt;
__device__ float g_table2[NCODE * 2];   // indexed BY CODE
__device__ int   g_bar_cnt;
__device__ int   g_bar_sense;

// ---------------------------------------------------------------------------
__device__ __forceinline__ float xla_tanh(float x) {
    const float kMax = 7.90531110763549805f;
    float xc = fmaxf(-kMax, fminf(x, kMax));
    float x2 = __fmul_rn(xc, xc);
    float p = -2.76076847742355e-16f;
    p = __fadd_rn(__fmul_rn(p, x2), 2.00018790482477e-13f);
    p = __fadd_rn(__fmul_rn(p, x2), -8.60467152213735e-11f);
    p = __fadd_rn(__fmul_rn(p, x2), 5.12229709037114e-08f);
    p = __fadd_rn(__fmul_rn(p, x2), 1.48572235717979e-05f);
    p = __fadd_rn(__fmul_rn(p, x2), 6.37261928875436e-04f);
    p = __fadd_rn(__fmul_rn(p, x2), 4.89352455891786e-03f);
    float num = __fmul_rn(xc, p);
    float q = 1.19825839466702e-06f;
    q = __fadd_rn(__fmul_rn(q, x2), 1.18534705686654e-04f);
    q = __fadd_rn(__fmul_rn(q, x2), 2.26843463243900e-03f);
    q = __fadd_rn(__fmul_rn(q, x2), 4.89352518554385e-03f);
    float r = __fdiv_rn(num, q);
    return (fabsf(x) < 0.0004f) ? x : r;
}

__device__ __forceinline__ float scale_in() {
    float m = __int_as_float(g_slots[0]);
    return fmaxf(__fdiv_rn(m, QMAXF), 1e-12f);
}
__device__ __forceinline__ float scale_act(int slot) {
    float m = __int_as_float(g_slots[slot]);
    float mh = xla_tanh(m);
    return fmaxf(__fdiv_rn(mh, QMAXF), 1e-12f);
}

__device__ __forceinline__ int q8(float v, float s) {
    float x = __fdiv_rn(v, s);
    x = fminf(fmaxf(x, -127.0f), 127.0f);
    return __float2int_rn(x);
}
__device__ __forceinline__ int q8f(float v, float s, float inv) {
    float r = __fmul_rn(v, inv);
    float rr = rintf(r);
    float d = fabsf(__fadd_rn(r, -rr));
    if (fabsf(d - 0.5f) < (4e-7f * fabsf(r) + 1e-9f))
        r = __fdiv_rn(v, s);
    r = fminf(fmaxf(r, -127.0f), 127.0f);
    return __float2int_rn(r);
}
__device__ __forceinline__ int pack4(int a, int b, int c, int d) {
    return (a & 0xFF) | ((b & 0xFF) << 8) | ((c & 0xFF) << 16) | ((d & 0xFF) << 24);
}
__device__ __forceinline__ float bias_q(float b, float sb) {
    float r = rintf(__fdiv_rn(b, sb));
    r = fminf(fmaxf(r, -128.0f), 127.0f);
    return __fmul_rn(r, sb);
}

__device__ __forceinline__ void build_Tp(float s, float* Tp) {
    int tid = threadIdx.x;
    if (tid < 130) {
        float v;
        if (tid == 0)        v = 0.0f;
        else if (tid >= 128) v = 3.0e38f;
        else {
            float tstar = __fmul_rn((float)tid - 0.5f, s);
            float r = __fdividef(1.0f + tstar, 1.0f - tstar);
            float y = 0.5f * __logf(r);
            #pragma unroll
            for (int it = 0; it < 2; it++) {
                float th = xla_tanh(y);
                float dv = fmaxf(1.0f - th * th, 1e-30f);
                y = y - __fdividef(th - tstar, dv);
            }
            v = y;
        }
        Tp[tid] = v;
    }
}

__device__ __forceinline__ void build_C(const float* Tp, unsigned char* C) {
    for (int e = threadIdx.x; e < CLUT; e += NTHR) {
        float yl = __uint_as_float(((unsigned)(e + CBASE)) << 17);
        int pos = 0;
        #pragma unroll
        for (int w = 64; w > 0; w >>= 1) {
            int j = pos + w;
            if (j <= 127 && Tp[j] <= yl) pos = j;
        }
        C[e] = (unsigned char)pos;
    }
}

__device__ __forceinline__ int qlut(float y, const float* Tp, const unsigned char* C) {
    float a = fabsf(y);
    unsigned u = __float_as_uint(fminf(a, 8.4999f));
    int idx = (int)(u >> 17) - CBASE;
    idx = idx < 0 ? 0 : idx;
    int c = C[idx];
    c += (a >= Tp[c + 1]) ? 1 : 0;
    c += (a >= Tp[c + 1]) ? 1 : 0;
    return (__float_as_uint(y) & 0x80000000u) ? -c : c;
}

__device__ __forceinline__ void mma_s8(int& d0, int& d1, int& d2, int& d3,
                                       int a0, int a1, int a2, int a3,
                                       int b0, int b1) {
    asm volatile(
        "mma.sync.aligned.m16n8k32.row.col.s32.s8.s8.s32 "
        "{%0,%1,%2,%3}, {%4,%5,%6,%7}, {%8,%9}, {%0,%1,%2,%3};"
        : "+r"(d0), "+r"(d1), "+r"(d2), "+r"(d3)
        : "r"(a0), "r"(a1), "r"(a2), "r"(a3), "r"(b0), "r"(b1));
}

__device__ __forceinline__ void grid_bar(int& sense) {
    int s = sense ^ 1;
    __threadfence();
    __syncthreads();
    if (threadIdx.x == 0) {
        int a = atomicAdd(&g_bar_cnt, 1);
        if (a == NBLK - 1) {
            g_bar_cnt = 0;
            __threadfence();
            g_bar_sense = s;
            __threadfence();
        } else {
            while (*((volatile int*)&g_bar_sense) != s)
                __nanosleep(64);
        }
    }
    __syncthreads();
    __threadfence();
    sense = s;
}

__device__ __forceinline__ void block_max_atomic(float v, int slot, float* s_red) {
    #pragma unroll
    for (int off = 16; off > 0; off >>= 1)
        v = fmaxf(v, __shfl_xor_sync(0xffffffffu, v, off));
    int w = threadIdx.x >> 5;
    if ((threadIdx.x & 31) == 0) s_red[w] = v;
    __syncthreads();
    if (threadIdx.x == 0) {
        float m = s_red[0];
        #pragma unroll
        for (int i = 1; i < NTHR / 32; i++) m = fmaxf(m, s_red[i]);
        atomicMax(&g_slots[slot], __float_as_int(m));
    }
    __syncthreads();
}

// ---------------------------------------------------------------------------
__global__ void k_prep(const float* __restrict__ z, const float* __restrict__ t,
                       const float* __restrict__ W1,
                       const float* __restrict__ W2, const float* __restrict__ W3,
                       const float* __restrict__ W4, const float* __restrict__ W5,
                       const float* __restrict__ W6, const float* __restrict__ Wout,
                       int n) {
    __shared__ float red[256];
    int tid = threadIdx.x;
    int bid = blockIdx.x;

    if (bid < 256) {
        float m = 0.0f;
        for (int i = bid * 256 + tid; i < n; i += 256 * 256)
            m = fmaxf(m, fmaxf(fabsf(z[i]), fabsf(t[i])));
        #pragma unroll
        for (int off = 16; off > 0; off >>= 1)
            m = fmaxf(m, __shfl_xor_sync(0xffffffffu, m, off));
        if ((tid & 31) == 0) red[tid >> 5] = m;
        __syncthreads();
        if (tid == 0) {
            float mm = red[0];
            #pragma unroll
            for (int i = 1; i < 8; i++) mm = fmaxf(mm, red[i]);
            atomicMax(&g_slots[0], __float_as_int(mm));
        }
        return;
    }
    if (bid == 263) {
        if (tid == 0) {
            g_cnt = 0;
            g_bar_cnt = 0;
            g_bar_sense = 0;
            g_gen = g_gen + 1;
        }
        return;
    }

    int l = bid - 256;
    const float* W;
    int cnt;
    if (l == 0)      { W = W1;   cnt = HID * 2; }
    else if (l == 6) { W = Wout; cnt = 2 * HID; }
    else {
        const float* Ws_[5] = {W2, W3, W4, W5, W6};
        W = Ws_[l - 1]; cnt = HID * HID;
    }

    float m = 0.0f;
    for (int i = tid; i < cnt; i += 256) m = fmaxf(m, fabsf(W[i]));
    red[tid] = m;
    __syncthreads();
    for (int s = 128; s > 0; s >>= 1) {
        if (tid < s) red[tid] = fmaxf(red[tid], red[tid + s]);
        __syncthreads();
    }
    __shared__ float s_sw;
    if (tid == 0) {
        float sw = fmaxf(__fdiv_rn(red[0], QMAXF), 1e-12f);
        g_sw[l] = sw;
        s_sw = sw;
    }
    __syncthreads();
    float sw = s_sw;

    if (l == 0) {
        for (int i = tid; i < HID * 2; i += 256)
            g_W1i[i] = q8(W[i], sw);
    } else if (l == 6) {
        for (int w = tid; w < 2 * KG; w += 256) {
            int o = w / KG, kg = w % KG;
            int base = o * HID + kg * 4;
            g_Wpo[o][kg] = pack4(q8(W[base + 0], sw), q8(W[base + 1], sw),
                                 q8(W[base + 2], sw), q8(W[base + 3], sw));
        }
    } else {
        for (int w = tid; w < KGP * 104; w += 256) {
            int kg = w / 104, c = w % 104;
            int p = 0;
            if (kg < KG && c < HID) {
                int base = c * HID + kg * 4;
                p = pack4(q8(W[base + 0], sw), q8(W[base + 1], sw),
                          q8(W[base + 2], sw), q8(W[base + 3], sw));
            }
            g_Wp[l - 1][kg][c] = p;
        }
    }
}

// ---------------------------------------------------------------------------
__global__ void __launch_bounds__(NTHR, 1)
k_mega(const float* __restrict__ z, const float* __restrict__ t,
       const float* __restrict__ b1, const float* __restrict__ b2,
       const float* __restrict__ b3, const float* __restrict__ b4,
       const float* __restrict__ b5, const float* __restrict__ b6,
       const float* __restrict__ bout, float* __restrict__ out, int n) {
    extern __shared__ char smem[];
    float*         s_yb  = (float*)(smem + YB_OFF);
    int*           s_Xs  = (int*)(smem + XS_OFF);
    int*           s_Ws  = (int*)(smem + WS_OFF);
    float*         s_Tp  = (float*)(smem + TP_OFF);
    unsigned char* s_C   = (unsigned char*)(smem + C_OFF);
    float*         s_bqs = (float*)(smem + BQ_OFF);
    float*         s_red = (float*)(smem + RED_OFF);
    float*         s_scl = (float*)(smem + SCL_OFF);

    int tid  = threadIdx.x;
    int gtid = blockIdx.x * NTHR + tid;
    int sense = 0;
    int gen = g_gen;

    // ---- P0: input codes + presence (x4 vectorized) -------------------------
    {
        if (tid == 0) {
            float sx = scale_in();
            s_scl[0] = sx;
            s_scl[1] = __fdiv_rn(1.0f, sx);
        }
        __syncthreads();
        float sx = s_scl[0];
        float inv = s_scl[1];
        int n4 = n >> 2;
        for (int i = gtid; i < n4; i += GSTRIDE) {
            float4 zv = ((const float4*)z)[i];
            float4 tv = ((const float4*)t)[i];
            int c0 = (q8f(zv.x, sx, inv) + 127) * 255 + (q8f(tv.x, sx, inv) + 127);
            int c1 = (q8f(zv.y, sx, inv) + 127) * 255 + (q8f(tv.y, sx, inv) + 127);
            int c2 = (q8f(zv.z, sx, inv) + 127) * 255 + (q8f(tv.z, sx, inv) + 127);
            int c3 = (q8f(zv.w, sx, inv) + 127) * 255 + (q8f(tv.w, sx, inv) + 127);
            ((int4*)g_code)[i] = make_int4(c0, c1, c2, c3);
            g_present[c0] = gen;
            g_present[c1] = gen;
            g_present[c2] = gen;
            g_present[c3] = gen;
        }
        for (int i = (n4 << 2) + gtid; i < n; i += GSTRIDE) {
            int zi = q8f(z[i], sx, inv);
            int ti = q8f(t[i], sx, inv);
            int c = (zi + 127) * 255 + (ti + 127);
            g_code[i] = c;
            g_present[c] = gen;
        }
    }
    grid_bar(sense);

    // ---- P1: warp-aggregated compaction ------------------------------------
    {
        int lane = tid & 31;
        unsigned lt = (1u << lane) - 1u;
        int bound = ((NCODE + GSTRIDE - 1) / GSTRIDE) * GSTRIDE;
        for (int c = gtid; c < bound; c += GSTRIDE) {
            bool p = (c < NCODE) && (g_present[c] == gen);
            unsigned mask = __ballot_sync(0xffffffffu, p);
            int base = 0;
            if (lane == 0 && mask) base = atomicAdd(&g_cnt, __popc(mask));
            base = __shfl_sync(0xffffffffu, base, 0);
            if (p) {
                int j = base + __popc(mask & lt);
                g_list[j] = c;
            }
        }
    }
    grid_bar(sense);
    int cnt = g_cnt;

    // block-owned contiguous rows
    int chunk = (cnt + NBLK - 1) / NBLK;
    chunk = chunk < CAP ? chunk : CAP;
    int rbeg = blockIdx.x * chunk;
    int rend = rbeg + chunk;
    rend = rend < cnt ? rend : cnt;
    int nloc = rend - rbeg;
    nloc = nloc > 0 ? nloc : 0;
    int slabs = (nloc + 15) >> 4;

    // ---- P2: layer 1 -> y1 into block-local smem ----------------------------
    {
        if (tid == 0) s_scl[0] = __fmul_rn(scale_in(), g_sw[0]);
        if (tid < HID * 2) s_Ws[tid] = g_W1i[tid];
        __syncthreads();
        float sb = s_scl[0];
        if (tid < HID) s_bqs[tid] = bias_q(b1[tid], sb);
        __syncthreads();

        float vmax = 0.0f;
        int tot = nloc * 25;
        for (int idx = tid; idx < tot; idx += NTHR) {
            int r  = idx / 25;
            int og = idx - r * 25;
            int c  = g_list[rbeg + r];
            int hi = c / 255;
            int zi = hi - 127;
            int ti = (c - hi * 255) - 127;
            float4 hv;
            float* hp = &hv.x;
            #pragma unroll
            for (int j = 0; j < 4; j++) {
                int o = og * 4 + j;
                int acc = zi * s_Ws[o * 2] + ti * s_Ws[o * 2 + 1];
                float y = (float)acc * sb + s_bqs[o];
                hp[j] = y;
                vmax = fmaxf(vmax, fabsf(y));
            }
            ((float4*)(s_yb + r * HID))[og] = hv;
        }
        block_max_atomic(vmax, 1, s_red);
    }
    grid_bar(sense);

    // ---- P3..P7: hidden layers 2..6 (smem-resident y, tensor cores) ---------
    {
        const float* biases[5] = {b2, b3, b4, b5, b6};
        int lane = tid & 31, wrp = tid >> 5;
        int g = lane >> 2, tg = lane & 3;
        int cA = (wrp << 3) + (tg << 1);
        bool mmaok = (wrp < 13);
        bool colok = mmaok && (cA < HID);

        for (int l = 1; l <= 5; l++) {
            const float* bias = biases[l - 1];

            if (tid == 0) {
                float sx = scale_act(l);
                s_scl[0] = sx;
                s_scl[1] = __fmul_rn(sx, g_sw[l]);
            }
            __syncthreads();
            float sx = s_scl[0];
            float sb = s_scl[1];

            const int* wp = &g_Wp[l - 1][0][0];
            for (int w = tid; w < KGP * 104; w += NTHR)
                s_Ws[w] = wp[w];
            if (tid < 104)
                s_bqs[tid] = (tid < HID) ? bias_q(bias[tid], sb) : 0.0f;
            build_Tp(sx, s_Tp);
            __syncthreads();
            build_C(s_Tp, s_C);
            __syncthreads();

            int wtot = (slabs << 4) * KGP;
            for (int w = tid; w < wtot; w += NTHR) {
                int r = w >> 5, kg = w & 31;
                int p = 0;
                if (kg < KG && r < nloc) {
                    float4 v = ((const float4*)(s_yb + r * HID))[kg];
                    p = pack4(qlut(v.x, s_Tp, s_C), qlut(v.y, s_Tp, s_C),
                              qlut(v.z, s_Tp, s_C), qlut(v.w, s_Tp, s_C));
                }
                s_Xs[kg * CAPP + r] = p;
            }
            __syncthreads();

            float vmax = 0.0f;
            if (mmaok) {
                int bf0[4], bf1[4];
                #pragma unroll
                for (int kc = 0; kc < 4; kc++) {
                    bf0[kc] = s_Ws[(8 * kc + tg) * 104 + (wrp << 3) + g];
                    bf1[kc] = s_Ws[(8 * kc + tg + 4) * 104 + (wrp << 3) + g];
                }
                float bqA = colok ? s_bqs[cA] : 0.0f;
                float bqB = colok ? s_bqs[cA + 1] : 0.0f;

                for (int mt = 0; mt < slabs; mt++) {
                    int d0 = 0, d1 = 0, d2 = 0, d3 = 0;
                    int rbase = (mt << 4) + g;
                    #pragma unroll
                    for (int kc = 0; kc < 4; kc++) {
                        int a0 = s_Xs[(8 * kc + tg) * CAPP + rbase];
                        int a1 = s_Xs[(8 * kc + tg) * CAPP + rbase + 8];
                        int a2 = s_Xs[(8 * kc + tg + 4) * CAPP + rbase];
                        int a3 = s_Xs[(8 * kc + tg + 4) * CAPP + rbase + 8];
                        mma_s8(d0, d1, d2, d3, a0, a1, a2, a3, bf0[kc], bf1[kc]);
                    }
                    if (colok) {
                        if (rbase < nloc) {
                            float y0 = (float)d0 * sb + bqA;
                            float y1 = (float)d1 * sb + bqB;
                            vmax = fmaxf(vmax, fmaxf(fabsf(y0), fabsf(y1)));
                            *(float2*)(s_yb + rbase * HID + cA) = make_float2(y0, y1);
                        }
                        if (rbase + 8 < nloc) {
                            float y2 = (float)d2 * sb + bqA;
                            float y3 = (float)d3 * sb + bqB;
                            vmax = fmaxf(vmax, fmaxf(fabsf(y2), fabsf(y3)));
                            *(float2*)(s_yb + (rbase + 8) * HID + cA) = make_float2(y2, y3);
                        }
                    }
                }
            }
            block_max_atomic(vmax, l + 1, s_red);
            grid_bar(sense);
        }
    }

    // ---- P8: output layer (smem y6 -> code-indexed table2) ------------------
    {
        if (tid == 0) {
            float sx = scale_act(6);
            s_scl[0] = sx;
            s_scl[1] = __fmul_rn(sx, g_sw[6]);
        }
        __syncthreads();
        float sx = s_scl[0];
        float sb = s_scl[1];
        float bq0 = bias_q(bout[0], sb);
        float bq1 = bias_q(bout[1], sb);

        build_Tp(sx, s_Tp);
        __syncthreads();
        build_C(s_Tp, s_C);
        __syncthreads();

        int wtot = (slabs << 4) * KGP;
        for (int w = tid; w < wtot; w += NTHR) {
            int r = w >> 5, kg = w & 31;
            int p = 0;
            if (kg < KG && r < nloc) {
                float4 v = ((const float4*)(s_yb + r * HID))[kg];
                p = pack4(qlut(v.x, s_Tp, s_C), qlut(v.y, s_Tp, s_C),
                          qlut(v.z, s_Tp, s_C), qlut(v.w, s_Tp, s_C));
            }
            s_Xs[kg * CAPP + r] = p;
        }
        __syncthreads();

        for (int idx = tid; idx < nloc * 2; idx += NTHR) {
            int r = idx >> 1, o = idx & 1;
            int acc = 0;
            #pragma unroll
            for (int kg = 0; kg < KG; kg++)
                acc = __dp4a(s_Xs[kg * CAPP + r], g_Wpo[o][kg], acc);
            int code = g_list[rbeg + r];
            g_table2[(size_t)code * 2 + o] = (float)acc * sb + (o ? bq1 : bq0);
        }
    }
    grid_bar(sense);

    // ---- P9: gather, single random hop (x4 vectorized) ----------------------
    {
        int n4 = n >> 2;
        for (int i = gtid; i < n4; i += GSTRIDE) {
            int4 c = ((const int4*)g_code)[i];
            float2 r0 = ((const float2*)g_table2)[c.x];
            float2 r1 = ((const float2*)g_table2)[c.y];
            float2 r2 = ((const float2*)g_table2)[c.z];
            float2 r3 = ((const float2*)g_table2)[c.w];
            ((float4*)out)[i * 2]     = make_float4(r0.x, r0.y, r1.x, r1.y);
            ((float4*)out)[i * 2 + 1] = make_float4(r2.x, r2.y, r3.x, r3.y);
        }
        for (int i = (n4 << 2) + gtid; i < n; i += GSTRIDE) {
            ((float2*)out)[i] = ((const float2*)g_table2)[g_code[i]];
        }
    }
}

// ---------------------------------------------------------------------------

extern "C" void kernel_launch(void* const* d_in, const int* in_sizes, int n_in,
                              void* d_out, int out_size) {
    const float* z    = (const float*)d_in[0];
    const float* t    = (const float*)d_in[1];
    const float* W1   = (const float*)d_in[2];
    const float* b1   = (const float*)d_in[3];
    const float* W2   = (const float*)d_in[4];
    const float* b2   = (const float*)d_in[5];
    const float* W3   = (const float*)d_in[6];
    const float* b3   = (const float*)d_in[7];
    const float* W4   = (const float*)d_in[8];
    const float* b4   = (const float*)d_in[9];
    const float* W5   = (const float*)d_in[10];
    const float* b5   = (const float*)d_in[11];
    const float* W6   = (const float*)d_in[12];
    const float* b6   = (const float*)d_in[13];
    const float* Wout = (const float*)d_in[14];
    const float* bout = (const float*)d_in[15];
    int n = in_sizes[0];

    static int configured = 0;
    if (!configured) {
        cudaFuncSetAttribute(k_mega, cudaFuncAttributeMaxDynamicSharedMemorySize,
                             SMEM_TOTAL);
        configured = 1;
    }

    k_prep<<<264, 256>>>(z, t, W1, W2, W3, W4, W5, W6, Wout, n);
    k_mega<<<NBLK, NTHR, SMEM_TOTAL>>>(z, t, b1, b2, b3, b4, b5, b6, bout,
                                       (float*)d_out, n);
}